// round 16
// baseline (speedup 1.0000x reference)
#include <cuda_runtime.h>
#include <cuda_fp16.h>
#include <math.h>
#include <stdint.h>

#define B_    2
#define T_    2048
#define D_    1024
#define HV_   16
#define HK_   8
#define KDIM_ 512
#define VDIM_ 1024
#define CONVD 2048
#define MIXW  3072          // fused GEMM width: [qkv 2048 | z 1024]
#define EPS_  1e-6f
#define NTOK  (B_*T_)       // 4096

// ======================= PTX helpers ======================================
__device__ __forceinline__ uint32_t smem_to_u32(const void* p) {
    uint32_t a;
    asm("{ .reg .u64 t; cvta.to.shared.u64 t, %1; cvt.u32.u64 %0, t; }" : "=r"(a) : "l"(p));
    return a;
}
__device__ __forceinline__ void ldsm_x4(uint32_t* r, uint32_t addr) {
    asm volatile("ldmatrix.sync.aligned.m8n8.x4.shared.b16 {%0,%1,%2,%3}, [%4];"
        : "=r"(r[0]), "=r"(r[1]), "=r"(r[2]), "=r"(r[3]) : "r"(addr));
}
__device__ __forceinline__ void mma16816f(float* c, const uint32_t* a, const uint32_t* b) {
    asm volatile("mma.sync.aligned.m16n8k16.row.col.f32.f16.f16.f32 "
        "{%0,%1,%2,%3}, {%4,%5,%6,%7}, {%8,%9}, {%0,%1,%2,%3};"
        : "+f"(c[0]), "+f"(c[1]), "+f"(c[2]), "+f"(c[3])
        : "r"(a[0]), "r"(a[1]), "r"(a[2]), "r"(a[3]), "r"(b[0]), "r"(b[1]));
}
#define CP16(sm, gp) asm volatile("cp.async.cg.shared.global [%0], [%1], 16;" :: "r"(sm), "l"(gp))
#define CP_COMMIT()  asm volatile("cp.async.commit_group;" ::: "memory")
#define CP_WAIT1()   asm volatile("cp.async.wait_group 1;" ::: "memory")
#define CP_WAIT0()   asm volatile("cp.async.wait_group 0;" ::: "memory")

// byte offset of (row, kc) 16B-unit in a [128 x 32fp16] tile, xor-swizzled
__device__ __forceinline__ uint32_t tunit(int row, int kc) {
    return (uint32_t)((row*4 + (kc ^ ((row >> 1) & 3))) * 16);
}

// ======================= static scratch ===================================
__device__ float g_mixed[NTOK*MIXW];        // [qkv | z]
__device__ float g_beta[NTOK*HV_];
__device__ float g_gg[NTOK*HV_];
__device__ float g_qn[NTOK*HK_*64];
__device__ float g_kn[NTOK*HK_*64];
__device__ float g_v[NTOK*VDIM_];
__device__ float g_o[NTOK*VDIM_];
__device__ __half g_hid[NTOK*D_];
__device__ __half g_w1[MIXW*D_];                      // [N=3072,K] fp16 single
__device__ __half g_woh[D_*VDIM_], g_wol[D_*VDIM_];   // [N=1024,K] hi/lo
__device__ __half g_on[NTOK*VDIM_];

// ======================= fp32 -> fp16 (elementwise) =======================
__global__ __launch_bounds__(256) void cvt_f2h(const float* __restrict__ src,
        __half* __restrict__ dst, int n4)
{
    int i = blockIdx.x*256 + threadIdx.x;
    if (i >= n4) return;
    float4 x = ((const float4*)src)[i];
    ((__half2*)dst)[2*i]   = __floats2half2_rn(x.x, x.y);
    ((__half2*)dst)[2*i+1] = __floats2half2_rn(x.z, x.w);
}

// ===== transpose + convert: W[K,N] fp32 -> Wt[N,K] fp16 (single) ==========
__global__ __launch_bounds__(256) void tconv_f2h(const float* __restrict__ W,
        __half* __restrict__ Wt, int K, int N)
{
    __shared__ float tile[32][33];
    int n0 = blockIdx.x*32, k0 = blockIdx.y*32;
    int tx = threadIdx.x, ty = threadIdx.y;   // 32 x 8
    #pragma unroll
    for (int j = 0; j < 32; j += 8)
        tile[ty+j][tx] = W[(long)(k0+ty+j)*N + n0 + tx];
    __syncthreads();
    #pragma unroll
    for (int j = 0; j < 32; j += 8)
        Wt[(long)(n0+ty+j)*K + k0 + tx] = __float2half(tile[tx][ty+j]);
}

// ===== transpose + convert: W[K,N] fp32 -> Wt[N,K] fp16 hi/lo =============
__global__ __launch_bounds__(256) void tconv_f2h2(const float* __restrict__ W,
        __half* __restrict__ Wh, __half* __restrict__ Wl, int K, int N)
{
    __shared__ float tile[32][33];
    int n0 = blockIdx.x*32, k0 = blockIdx.y*32;
    int tx = threadIdx.x, ty = threadIdx.y;   // 32 x 8
    #pragma unroll
    for (int j = 0; j < 32; j += 8)
        tile[ty+j][tx] = W[(long)(k0+ty+j)*N + n0 + tx];
    __syncthreads();
    #pragma unroll
    for (int j = 0; j < 32; j += 8) {
        float x = tile[tx][ty+j];
        __half h = __float2half(x);
        long o = (long)(n0+ty+j)*K + k0 + tx;
        Wh[o] = h;
        Wl[o] = __float2half(x - __half2float(h));
    }
}

// =============== GEMM variant 0: single fp16 MMA ==========================
#define STG1 16384   // A 8K | B 8K
__global__ __launch_bounds__(256) void gemm_h1(
    const __half* __restrict__ A, const __half* __restrict__ Bm,
    float* __restrict__ C, int M, int N, int K)
{
    extern __shared__ __align__(128) char smem[];
    uint32_t sb = smem_to_u32(smem);
    int tid = threadIdx.x, lane = tid & 31, wid = tid >> 5;
    int wm = wid & 3, wn = wid >> 2;        // 4 x 2 warp grid (32x64 per warp)
    int bx = blockIdx.x, by = blockIdx.y;
    const int NC = K >> 5;

    float acc[2][8][4];
    #pragma unroll
    for (int i = 0; i < 2; i++)
        #pragma unroll
        for (int j = 0; j < 8; j++)
            #pragma unroll
            for (int q = 0; q < 4; q++) acc[i][j][q] = 0.f;

    #define LOAD_H1(ic, s) do { \
        long kof = (long)(ic) * 32; \
        uint32_t st = sb + (s)*STG1; \
        _Pragma("unroll") \
        for (int j = 0; j < 2; j++) { \
            int u = tid + j*256; \
            int row = u >> 2, kc = u & 3; \
            CP16(st + tunit(row, kc), A + (long)(by*128 + row)*K + kof + kc*8); \
        } \
        _Pragma("unroll") \
        for (int j = 0; j < 2; j++) { \
            int u = tid + j*256; \
            int row = u >> 2, kc = u & 3; \
            CP16(st + 8192 + tunit(row, kc), Bm + (long)(bx*128 + row)*K + kof + kc*8); \
        } \
        CP_COMMIT(); \
    } while (0)

    LOAD_H1(0, 0);
    LOAD_H1(1, 1);

    int lr = lane & 15, lk = lane >> 4;
    for (int ic = 0; ic < NC; ic++) {
        int s = ic - (ic/3)*3;
        if (ic + 1 < NC) CP_WAIT1(); else CP_WAIT0();
        __syncthreads();
        if (ic + 2 < NC) { int s2 = (ic+2) - ((ic+2)/3)*3; LOAD_H1(ic + 2, s2); }

        uint32_t pA = sb + s*STG1, pB = pA + 8192;
        #pragma unroll
        for (int ks = 0; ks < 2; ks++) {
            uint32_t a[2][4], b[8][2];
            #pragma unroll
            for (int mt = 0; mt < 2; mt++)
                ldsm_x4(a[mt], pA + tunit(wm*32 + mt*16 + lr, ks*2 + lk));
            #pragma unroll
            for (int bp = 0; bp < 4; bp++) {
                uint32_t t[4];
                ldsm_x4(t, pB + tunit(wn*64 + bp*16 + lr, ks*2 + lk));
                b[bp*2][0]=t[0]; b[bp*2][1]=t[2]; b[bp*2+1][0]=t[1]; b[bp*2+1][1]=t[3];
            }
            #pragma unroll
            for (int mt = 0; mt < 2; mt++)
                #pragma unroll
                for (int nt = 0; nt < 8; nt++)
                    mma16816f(acc[mt][nt], a[mt], b[nt]);
        }
    }

    #pragma unroll
    for (int mt = 0; mt < 2; mt++)
        #pragma unroll
        for (int nt = 0; nt < 8; nt++) {
            long r = by*128 + wm*32 + mt*16 + (lane >> 2);
            long c = bx*128 + wn*64 + nt*8 + (lane & 3)*2;
            *(float2*)&C[r*N + c]     = make_float2(acc[mt][nt][0], acc[mt][nt][1]);
            *(float2*)&C[(r+8)*N + c] = make_float2(acc[mt][nt][2], acc[mt][nt][3]);
        }
}

// =============== GEMM variant 1: A fp16, W split hi/lo (2 MMA) ===========
#define STG2 24576   // A 8K | Bh 8K | Bl 8K
__global__ __launch_bounds__(256) void gemm_w2(
    const __half* __restrict__ A, const __half* __restrict__ Bh,
    const __half* __restrict__ Bl, float* __restrict__ C, int M, int N, int K)
{
    extern __shared__ __align__(128) char smem[];
    uint32_t sb = smem_to_u32(smem);
    int tid = threadIdx.x, lane = tid & 31, wid = tid >> 5;
    int wm = wid & 3, wn = wid >> 2;
    int bx = blockIdx.x, by = blockIdx.y;
    const int NC = K >> 5;

    float acc[2][8][4];
    #pragma unroll
    for (int i = 0; i < 2; i++)
        #pragma unroll
        for (int j = 0; j < 8; j++)
            #pragma unroll
            for (int q = 0; q < 4; q++) acc[i][j][q] = 0.f;

    #define LOAD_W2(ic, s) do { \
        long kof = (long)(ic) * 32; \
        uint32_t st = sb + (s)*STG2; \
        _Pragma("unroll") \
        for (int j = 0; j < 2; j++) { \
            int u = tid + j*256; int row = u >> 2, kc = u & 3; \
            uint32_t sw = tunit(row, kc); \
            long ao = (long)(by*128 + row)*K + kof + kc*8; \
            long bo = (long)(bx*128 + row)*K + kof + kc*8; \
            CP16(st + sw,          A  + ao); \
            CP16(st + 8192 + sw,   Bh + bo); \
            CP16(st + 16384 + sw,  Bl + bo); \
        } \
        CP_COMMIT(); \
    } while (0)

    LOAD_W2(0, 0);
    LOAD_W2(1, 1);

    int lr = lane & 15, lk = lane >> 4;
    for (int ic = 0; ic < NC; ic++) {
        int s = ic - (ic/3)*3;
        if (ic + 1 < NC) CP_WAIT1(); else CP_WAIT0();
        __syncthreads();
        if (ic + 2 < NC) { int s2 = (ic+2) - ((ic+2)/3)*3; LOAD_W2(ic + 2, s2); }

        uint32_t pA = sb + s*STG2, pBh = pA + 8192, pBl = pA + 16384;
        #pragma unroll
        for (int ks = 0; ks < 2; ks++) {
            uint32_t a[2][4], bh[8][2], bl[8][2];
            #pragma unroll
            for (int mt = 0; mt < 2; mt++)
                ldsm_x4(a[mt], pA + tunit(wm*32 + mt*16 + lr, ks*2 + lk));
            #pragma unroll
            for (int bp = 0; bp < 4; bp++) {
                uint32_t off = tunit(wn*64 + bp*16 + lr, ks*2 + lk);
                uint32_t t[4];
                ldsm_x4(t, pBh + off);
                bh[bp*2][0]=t[0]; bh[bp*2][1]=t[2]; bh[bp*2+1][0]=t[1]; bh[bp*2+1][1]=t[3];
                ldsm_x4(t, pBl + off);
                bl[bp*2][0]=t[0]; bl[bp*2][1]=t[2]; bl[bp*2+1][0]=t[1]; bl[bp*2+1][1]=t[3];
            }
            #pragma unroll
            for (int mt = 0; mt < 2; mt++)
                #pragma unroll
                for (int nt = 0; nt < 8; nt++) {
                    mma16816f(acc[mt][nt], a[mt], bh[nt]);
                    mma16816f(acc[mt][nt], a[mt], bl[nt]);
                }
        }
    }

    #pragma unroll
    for (int mt = 0; mt < 2; mt++)
        #pragma unroll
        for (int nt = 0; nt < 8; nt++) {
            long r = by*128 + wm*32 + mt*16 + (lane >> 2);
            long c = bx*128 + wn*64 + nt*8 + (lane & 3)*2;
            *(float2*)&C[r*N + c]     = make_float2(acc[mt][nt][0], acc[mt][nt][1]);
            *(float2*)&C[(r+8)*N + c] = make_float2(acc[mt][nt][2], acc[mt][nt][3]);
        }
}

// ======================= beta / g projections =============================
__global__ __launch_bounds__(256) void betag_kernel(
    const float* __restrict__ hid, const float* __restrict__ Wb,
    const float* __restrict__ Wa, const float* __restrict__ dtb,
    const float* __restrict__ Alog)
{
    int row = blockIdx.x;
    int tid = threadIdx.x;
    __shared__ float sh[D_];
    __shared__ float red[256];
    *(float4*)&sh[tid*4] = *(const float4*)(hid + (long)row*D_ + tid*4);
    __syncthreads();
    int c  = tid & 31, sg = tid >> 5;
    const float* W = (c < 16) ? Wb : Wa;
    int cc = c & 15, k0 = sg * 128;
    float acc = 0.f;
    #pragma unroll 8
    for (int k = 0; k < 128; k++)
        acc = fmaf(sh[k0 + k], W[(k0 + k)*HV_ + cc], acc);
    red[tid] = acc;
    __syncthreads();
    if (tid < 32) {
        float s = 0.f;
        #pragma unroll
        for (int si = 0; si < 8; si++) s += red[si*32 + c];
        if (c < 16) g_beta[(long)row*HV_ + cc] = 1.f / (1.f + expf(-s));
        else {
            float x  = s + dtb[cc];
            float sp = (x > 20.f) ? x : log1pf(expf(x));
            g_gg[(long)row*HV_ + cc] = -expf(Alog[cc]) * sp;
        }
    }
}

// ===== causal conv + SiLU + split + l2norm; 4 timesteps per block =========
__global__ __launch_bounds__(256) void conv_kernel(const float* __restrict__ convw)
{
    int t0 = blockIdx.x * 4, b = blockIdx.y;
    int tid = threadIdx.x;
    __shared__ float sy[4][CONVD];

    #pragma unroll
    for (int jt = 0; jt < 4; jt++) {
        int t = t0 + jt;
        long row = (long)(b*T_ + t);
        #pragma unroll
        for (int j = 0; j < 8; j++) {
            int c = tid + j*256;
            float4 w = *(const float4*)(convw + c*4);
            float acc = g_mixed[row*MIXW + c] * w.w;
            if (t >= 1) acc = fmaf(g_mixed[(row-1)*MIXW + c], w.z, acc);
            if (t >= 2) acc = fmaf(g_mixed[(row-2)*MIXW + c], w.y, acc);
            if (t >= 3) acc = fmaf(g_mixed[(row-3)*MIXW + c], w.x, acc);
            sy[jt][c] = acc / (1.f + __expf(-acc));
        }
    }
    __syncthreads();

    int wrp = tid >> 5, lane = tid & 31;
    #pragma unroll
    for (int jt = 0; jt < 4; jt++) {
        long row = (long)(b*T_ + t0 + jt);
        {
            float y0 = sy[jt][wrp*64 + lane], y1 = sy[jt][wrp*64 + 32 + lane];
            float ss = y0*y0 + y1*y1;
            #pragma unroll
            for (int off = 16; off; off >>= 1) ss += __shfl_xor_sync(0xffffffffu, ss, off);
            float rs = rsqrtf(ss + EPS_) * 0.125f;
            g_qn[(row*HK_ + wrp)*64 + lane]      = y0 * rs;
            g_qn[(row*HK_ + wrp)*64 + 32 + lane] = y1 * rs;
        }
        {
            float y0 = sy[jt][KDIM_ + wrp*64 + lane], y1 = sy[jt][KDIM_ + wrp*64 + 32 + lane];
            float ss = y0*y0 + y1*y1;
            #pragma unroll
            for (int off = 16; off; off >>= 1) ss += __shfl_xor_sync(0xffffffffu, ss, off);
            float rs = rsqrtf(ss + EPS_);
            g_kn[(row*HK_ + wrp)*64 + lane]      = y0 * rs;
            g_kn[(row*HK_ + wrp)*64 + 32 + lane] = y1 * rs;
        }
        #pragma unroll
        for (int j = 0; j < 4; j++) {
            int c = tid + j*256;
            g_v[row*VDIM_ + c] = sy[jt][1024 + c];
        }
    }
}

// ==== gated delta recurrence: 2 independent head-chains per warp (ILP) ====
// 1024 tasks = (b, h, 2-col group). Warp w handles tasks (b,h0,cg2) and
// (b,h0+8,cg2) — two independent recurrent chains interleaved in one
// instruction stream, so each chain's shfl/FMA latency hides the other's.
// Lane layout per task: colIdx = lane>>4 (0..1), rseg = lane&15; 4 rows/lane.
// Reductions over 16 lanes (xor 1,2,4,8 — stays within rseg bits).
#define PF 4
__global__ __launch_bounds__(128) void recurrence_kernel()
{
    int w = blockIdx.x*4 + (threadIdx.x >> 5);    // 0..511
    int lane = threadIdx.x & 31;
    int b  = w >> 8;                // 0..1
    int h0 = (w >> 5) & 7;          // 0..7
    int cg = w & 31;                // 0..31 (2-col groups)
    int colIdx = lane >> 4;         // 0..1
    int rseg = lane & 15;           // 0..15 -> rows rseg*4..rseg*4+3
    int col = cg*2 + colIdx;

    const long qs = (long)HK_*64, vs = (long)HV_*64, gs = HV_;
    const float *kb[2], *qb[2], *vb[2], *gb[2], *bb[2];
    float *ob[2];
    #pragma unroll
    for (int x = 0; x < 2; x++) {
        int h = h0 + x*8, kh = h >> 1;
        kb[x] = g_kn   + ((long)(b*T_)*HK_ + kh)*64 + rseg*4;
        qb[x] = g_qn   + ((long)(b*T_)*HK_ + kh)*64 + rseg*4;
        vb[x] = g_v    + ((long)(b*T_)*HV_ + h)*64 + col;
        gb[x] = g_gg   + (long)(b*T_)*HV_ + h;
        bb[x] = g_beta + (long)(b*T_)*HV_ + h;
        ob[x] = g_o    + ((long)(b*T_)*HV_ + h)*64 + col;
    }

    float S[2][4], kprev[2][4], dprev[2] = {0.f, 0.f};
    #pragma unroll
    for (int x = 0; x < 2; x++)
        #pragma unroll
        for (int i = 0; i < 4; i++) { S[x][i] = 0.f; kprev[x][i] = 0.f; }

    float4 pk[2][PF], pq[2][PF];
    float  pv[2][PF], pg[2][PF], pb[2][PF];
    #pragma unroll
    for (int j = 0; j < PF; j++)
        #pragma unroll
        for (int x = 0; x < 2; x++) {
            long o = j;
            pk[x][j] = *(const float4*)(kb[x] + o*qs);
            pq[x][j] = *(const float4*)(qb[x] + o*qs);
            pv[x][j] = vb[x][o*vs];  pg[x][j] = gb[x][o*gs];  pb[x][j] = bb[x][o*gs];
        }

    for (int t0 = 0; t0 < T_; t0 += PF) {
        #pragma unroll
        for (int j = 0; j < PF; j++) {
            int t = t0 + j;
            float4 k4[2], q4[2];
            float vv[2], gv[2], bv[2];
            #pragma unroll
            for (int x = 0; x < 2; x++) {
                k4[x] = pk[x][j]; q4[x] = pq[x][j];
                vv[x] = pv[x][j]; gv[x] = pg[x][j]; bv[x] = pb[x][j];
            }
            if (t + PF < T_) {
                long o = (long)(t + PF);
                #pragma unroll
                for (int x = 0; x < 2; x++) {
                    pk[x][j] = *(const float4*)(kb[x] + o*qs);
                    pq[x][j] = *(const float4*)(qb[x] + o*qs);
                    pv[x][j] = vb[x][o*vs];  pg[x][j] = gb[x][o*gs];  pb[x][j] = bb[x][o*gs];
                }
            }

            float eg[2], kvp[2], op[2], qkp[2];
            #pragma unroll
            for (int x = 0; x < 2; x++) eg[x] = __expf(gv[x]);

            #pragma unroll
            for (int x = 0; x < 2; x++) {
                float kc[4] = {k4[x].x, k4[x].y, k4[x].z, k4[x].w};
                float qc[4] = {q4[x].x, q4[x].y, q4[x].z, q4[x].w};
                float kv = 0.f, o2 = 0.f, qk = 0.f;
                #pragma unroll
                for (int i = 0; i < 4; i++) {
                    S[x][i] = fmaf(kprev[x][i], dprev[x], S[x][i]) * eg[x];
                    kv = fmaf(kc[i], S[x][i], kv);
                    o2 = fmaf(qc[i], S[x][i], o2);
                    qk = fmaf(qc[i], kc[i], qk);
                    kprev[x][i] = kc[i];
                }
                kvp[x] = kv; op[x] = o2; qkp[x] = qk;
            }
            // interleaved 16-lane reductions: both chains' shfls overlap
            #pragma unroll
            for (int off = 1; off < 16; off <<= 1) {
                #pragma unroll
                for (int x = 0; x < 2; x++) {
                    kvp[x] += __shfl_xor_sync(0xffffffffu, kvp[x], off);
                    op[x]  += __shfl_xor_sync(0xffffffffu, op[x],  off);
                    qkp[x] += __shfl_xor_sync(0xffffffffu, qkp[x], off);
                }
            }
            #pragma unroll
            for (int x = 0; x < 2; x++) {
                float delta = (vv[x] - kvp[x]) * bv[x];
                if (rseg == 0) ob[x][(long)t*vs] = fmaf(qkp[x], delta, op[x]);
                dprev[x] = delta;
            }
        }
    }
}

// ========== gated RMSNorm * silu(z), emits fp16 for GEMM3 =================
__global__ __launch_bounds__(256) void gnorm_kernel(const float* __restrict__ nw)
{
    int t = blockIdx.x, b = blockIdx.y;
    long row = (long)(b*T_ + t);
    int wrp = threadIdx.x >> 5, lane = threadIdx.x & 31;
    #pragma unroll
    for (int hh = wrp; hh < HV_; hh += 8) {
        float o0 = g_o[(row*HV_ + hh)*64 + lane];
        float o1 = g_o[(row*HV_ + hh)*64 + 32 + lane];
        float ss = o0*o0 + o1*o1;
        #pragma unroll
        for (int off = 16; off; off >>= 1) ss += __shfl_xor_sync(0xffffffffu, ss, off);
        float rs = rsqrtf(ss * (1.f/64.f) + EPS_);
        float z0 = g_mixed[row*MIXW + CONVD + hh*64 + lane];
        float z1 = g_mixed[row*MIXW + CONVD + hh*64 + 32 + lane];
        float v0 = o0 * rs * nw[lane]      * (z0 / (1.f + __expf(-z0)));
        float v1 = o1 * rs * nw[lane + 32] * (z1 / (1.f + __expf(-z1)));
        long i0 = row*VDIM_ + hh*64 + lane;
        g_on[i0]      = __float2half(v0);
        g_on[i0 + 32] = __float2half(v1);
    }
}

// ==========================================================================
extern "C" void kernel_launch(void* const* d_in, const int* in_sizes, int n_in,
                              void* d_out, int out_size)
{
    (void)in_sizes; (void)n_in; (void)out_size;
    const float* hid   = (const float*)d_in[0];
    const float* Wqkv  = (const float*)d_in[1];
    const float* Wz    = (const float*)d_in[2];
    const float* Wb    = (const float*)d_in[3];
    const float* Wa    = (const float*)d_in[4];
    const float* dtb   = (const float*)d_in[5];
    const float* Alog  = (const float*)d_in[6];
    const float* convw = (const float*)d_in[7];
    const float* nw    = (const float*)d_in[8];
    const float* Wout  = (const float*)d_in[9];
    float* out = (float*)d_out;

    float *mixed;
    __half *hh, *w1, *woh, *wol, *on;
    cudaGetSymbolAddress((void**)&mixed, g_mixed);
    cudaGetSymbolAddress((void**)&hh,  g_hid);
    cudaGetSymbolAddress((void**)&w1,  g_w1);
    cudaGetSymbolAddress((void**)&woh, g_woh);  cudaGetSymbolAddress((void**)&wol, g_wol);
    cudaGetSymbolAddress((void**)&on,  g_on);

    static int smem_set = 0;
    if (!smem_set) {
        cudaFuncSetAttribute(gemm_h1, cudaFuncAttributeMaxDynamicSharedMemorySize, 3*STG1);
        cudaFuncSetAttribute(gemm_w2, cudaFuncAttributeMaxDynamicSharedMemorySize, 3*STG2);
        smem_set = 1;
    }

    // conversions
    cvt_f2h<<<(NTOK*D_/4 + 255)/256, 256>>>(hid, hh, NTOK*D_/4);
    tconv_f2h<<<dim3(CONVD/32, D_/32), dim3(32,8)>>>(Wqkv, w1, D_, CONVD);
    tconv_f2h<<<dim3(VDIM_/32, D_/32), dim3(32,8)>>>(Wz, w1 + (long)CONVD*D_, D_, VDIM_);
    tconv_f2h2<<<dim3(D_/32, VDIM_/32), dim3(32,8)>>>(Wout, woh, wol, VDIM_, D_);

    // fused GEMM: [mixed | z] = hid @ [Wqkv | Wz]   (single fp16 MMA)
    gemm_h1<<<dim3(MIXW/128, NTOK/128), 256, 3*STG1>>>(hh, w1, mixed, NTOK, MIXW, D_);
    // beta / g
    betag_kernel<<<NTOK, 256>>>(hid, Wb, Wa, dtb, Alog);
    // conv + silu + split + l2norm  (4 timesteps per block)
    conv_kernel<<<dim3(T_/4, B_), 256>>>(convw);
    // recurrence (2 head-chains per warp, 128 blocks x 4 warps)
    recurrence_kernel<<<128, 128>>>();
    // gated RMSNorm -> fp16
    gnorm_kernel<<<dim3(T_, B_), 256>>>(nw);
    // GEMM3: out = on @ Wout  (W compensated, 2 MMA)
    gemm_w2<<<dim3(D_/128, NTOK/128), 256, 3*STG2>>>(on, woh, wol, out, NTOK, D_, VDIM_);
}

// round 17
// speedup vs baseline: 1.0379x; 1.0379x over previous
#include <cuda_runtime.h>
#include <cuda_fp16.h>
#include <math.h>
#include <stdint.h>

#define B_    2
#define T_    2048
#define D_    1024
#define HV_   16
#define HK_   8
#define KDIM_ 512
#define VDIM_ 1024
#define CONVD 2048
#define MIXW  3072          // fused GEMM width: [qkv 2048 | z 1024]
#define EPS_  1e-6f
#define NTOK  (B_*T_)       // 4096

// ======================= PTX helpers ======================================
__device__ __forceinline__ uint32_t smem_to_u32(const void* p) {
    uint32_t a;
    asm("{ .reg .u64 t; cvta.to.shared.u64 t, %1; cvt.u32.u64 %0, t; }" : "=r"(a) : "l"(p));
    return a;
}
__device__ __forceinline__ void ldsm_x4(uint32_t* r, uint32_t addr) {
    asm volatile("ldmatrix.sync.aligned.m8n8.x4.shared.b16 {%0,%1,%2,%3}, [%4];"
        : "=r"(r[0]), "=r"(r[1]), "=r"(r[2]), "=r"(r[3]) : "r"(addr));
}
__device__ __forceinline__ void mma16816f(float* c, const uint32_t* a, const uint32_t* b) {
    asm volatile("mma.sync.aligned.m16n8k16.row.col.f32.f16.f16.f32 "
        "{%0,%1,%2,%3}, {%4,%5,%6,%7}, {%8,%9}, {%0,%1,%2,%3};"
        : "+f"(c[0]), "+f"(c[1]), "+f"(c[2]), "+f"(c[3])
        : "r"(a[0]), "r"(a[1]), "r"(a[2]), "r"(a[3]), "r"(b[0]), "r"(b[1]));
}
#define CP16(sm, gp) asm volatile("cp.async.cg.shared.global [%0], [%1], 16;" :: "r"(sm), "l"(gp))
#define CP_COMMIT()  asm volatile("cp.async.commit_group;" ::: "memory")
#define CP_WAIT1()   asm volatile("cp.async.wait_group 1;" ::: "memory")
#define CP_WAIT0()   asm volatile("cp.async.wait_group 0;" ::: "memory")

// byte offset of (row, kc) 16B-unit in a [128 x 32fp16] tile, xor-swizzled
__device__ __forceinline__ uint32_t tunit(int row, int kc) {
    return (uint32_t)((row*4 + (kc ^ ((row >> 1) & 3))) * 16);
}

// ======================= static scratch ===================================
__device__ float g_mixed[NTOK*MIXW];        // [qkv | z]
__device__ float g_beta[NTOK*HV_];
__device__ float g_gg[NTOK*HV_];
__device__ float g_qn[NTOK*HK_*64];
__device__ float g_kn[NTOK*HK_*64];
__device__ float g_v[NTOK*VDIM_];
__device__ float g_o[NTOK*VDIM_];
__device__ __half g_hid[NTOK*D_];
__device__ __half g_w1[MIXW*D_];                      // [N=3072,K] fp16 single
__device__ __half g_woh[D_*VDIM_], g_wol[D_*VDIM_];   // [N=1024,K] hi/lo
__device__ __half g_on[NTOK*VDIM_];

// ===== fused: fp32->fp16 row convert + beta/g projections =================
// One block per token row: hid row staged in smem once, used for both the
// fp16 conversion and the beta/g dot products (removes a second 16MB read).
__global__ __launch_bounds__(256) void cvtbg_kernel(
    const float* __restrict__ hid, __half* __restrict__ dst,
    const float* __restrict__ Wb, const float* __restrict__ Wa,
    const float* __restrict__ dtb, const float* __restrict__ Alog)
{
    int row = blockIdx.x;       // 0..4095
    int tid = threadIdx.x;
    __shared__ float sh[D_];
    __shared__ float red[256];

    float4 x = *(const float4*)(hid + (long)row*D_ + tid*4);
    *(float4*)&sh[tid*4] = x;
    ((__half2*)dst)[(long)row*(D_/2) + tid*2]     = __floats2half2_rn(x.x, x.y);
    ((__half2*)dst)[(long)row*(D_/2) + tid*2 + 1] = __floats2half2_rn(x.z, x.w);
    __syncthreads();

    int c  = tid & 31, sg = tid >> 5;
    const float* W = (c < 16) ? Wb : Wa;
    int cc = c & 15, k0 = sg * 128;
    float acc = 0.f;
    #pragma unroll 8
    for (int k = 0; k < 128; k++)
        acc = fmaf(sh[k0 + k], W[(k0 + k)*HV_ + cc], acc);
    red[tid] = acc;
    __syncthreads();
    if (tid < 32) {
        float s = 0.f;
        #pragma unroll
        for (int si = 0; si < 8; si++) s += red[si*32 + c];
        if (c < 16) g_beta[(long)row*HV_ + cc] = 1.f / (1.f + expf(-s));
        else {
            float x2  = s + dtb[cc];
            float sp = (x2 > 20.f) ? x2 : log1pf(expf(x2));
            g_gg[(long)row*HV_ + cc] = -expf(Alog[cc]) * sp;
        }
    }
}

// ===== transpose + convert: W[K,N] fp32 -> Wt[N,K] fp16 (single) ==========
__global__ __launch_bounds__(256) void tconv_f2h(const float* __restrict__ W,
        __half* __restrict__ Wt, int K, int N)
{
    __shared__ float tile[32][33];
    int n0 = blockIdx.x*32, k0 = blockIdx.y*32;
    int tx = threadIdx.x, ty = threadIdx.y;   // 32 x 8
    #pragma unroll
    for (int j = 0; j < 32; j += 8)
        tile[ty+j][tx] = W[(long)(k0+ty+j)*N + n0 + tx];
    __syncthreads();
    #pragma unroll
    for (int j = 0; j < 32; j += 8)
        Wt[(long)(n0+ty+j)*K + k0 + tx] = __float2half(tile[tx][ty+j]);
}

// ===== transpose + convert: W[K,N] fp32 -> Wt[N,K] fp16 hi/lo =============
__global__ __launch_bounds__(256) void tconv_f2h2(const float* __restrict__ W,
        __half* __restrict__ Wh, __half* __restrict__ Wl, int K, int N)
{
    __shared__ float tile[32][33];
    int n0 = blockIdx.x*32, k0 = blockIdx.y*32;
    int tx = threadIdx.x, ty = threadIdx.y;   // 32 x 8
    #pragma unroll
    for (int j = 0; j < 32; j += 8)
        tile[ty+j][tx] = W[(long)(k0+ty+j)*N + n0 + tx];
    __syncthreads();
    #pragma unroll
    for (int j = 0; j < 32; j += 8) {
        float x = tile[tx][ty+j];
        __half h = __float2half(x);
        long o = (long)(n0+ty+j)*K + k0 + tx;
        Wh[o] = h;
        Wl[o] = __float2half(x - __half2float(h));
    }
}

// =============== GEMM variant 0: single fp16 MMA ==========================
#define STG1 16384   // A 8K | B 8K
__global__ __launch_bounds__(256) void gemm_h1(
    const __half* __restrict__ A, const __half* __restrict__ Bm,
    float* __restrict__ C, int M, int N, int K)
{
    extern __shared__ __align__(128) char smem[];
    uint32_t sb = smem_to_u32(smem);
    int tid = threadIdx.x, lane = tid & 31, wid = tid >> 5;
    int wm = wid & 3, wn = wid >> 2;        // 4 x 2 warp grid (32x64 per warp)
    int bx = blockIdx.x, by = blockIdx.y;
    const int NC = K >> 5;

    float acc[2][8][4];
    #pragma unroll
    for (int i = 0; i < 2; i++)
        #pragma unroll
        for (int j = 0; j < 8; j++)
            #pragma unroll
            for (int q = 0; q < 4; q++) acc[i][j][q] = 0.f;

    #define LOAD_H1(ic, s) do { \
        long kof = (long)(ic) * 32; \
        uint32_t st = sb + (s)*STG1; \
        _Pragma("unroll") \
        for (int j = 0; j < 2; j++) { \
            int u = tid + j*256; \
            int row = u >> 2, kc = u & 3; \
            CP16(st + tunit(row, kc), A + (long)(by*128 + row)*K + kof + kc*8); \
        } \
        _Pragma("unroll") \
        for (int j = 0; j < 2; j++) { \
            int u = tid + j*256; \
            int row = u >> 2, kc = u & 3; \
            CP16(st + 8192 + tunit(row, kc), Bm + (long)(bx*128 + row)*K + kof + kc*8); \
        } \
        CP_COMMIT(); \
    } while (0)

    LOAD_H1(0, 0);
    LOAD_H1(1, 1);

    int lr = lane & 15, lk = lane >> 4;
    for (int ic = 0; ic < NC; ic++) {
        int s = ic - (ic/3)*3;
        if (ic + 1 < NC) CP_WAIT1(); else CP_WAIT0();
        __syncthreads();
        if (ic + 2 < NC) { int s2 = (ic+2) - ((ic+2)/3)*3; LOAD_H1(ic + 2, s2); }

        uint32_t pA = sb + s*STG1, pB = pA + 8192;
        #pragma unroll
        for (int ks = 0; ks < 2; ks++) {
            uint32_t a[2][4], b[8][2];
            #pragma unroll
            for (int mt = 0; mt < 2; mt++)
                ldsm_x4(a[mt], pA + tunit(wm*32 + mt*16 + lr, ks*2 + lk));
            #pragma unroll
            for (int bp = 0; bp < 4; bp++) {
                uint32_t t[4];
                ldsm_x4(t, pB + tunit(wn*64 + bp*16 + lr, ks*2 + lk));
                b[bp*2][0]=t[0]; b[bp*2][1]=t[2]; b[bp*2+1][0]=t[1]; b[bp*2+1][1]=t[3];
            }
            #pragma unroll
            for (int mt = 0; mt < 2; mt++)
                #pragma unroll
                for (int nt = 0; nt < 8; nt++)
                    mma16816f(acc[mt][nt], a[mt], b[nt]);
        }
    }

    #pragma unroll
    for (int mt = 0; mt < 2; mt++)
        #pragma unroll
        for (int nt = 0; nt < 8; nt++) {
            long r = by*128 + wm*32 + mt*16 + (lane >> 2);
            long c = bx*128 + wn*64 + nt*8 + (lane & 3)*2;
            *(float2*)&C[r*N + c]     = make_float2(acc[mt][nt][0], acc[mt][nt][1]);
            *(float2*)&C[(r+8)*N + c] = make_float2(acc[mt][nt][2], acc[mt][nt][3]);
        }
}

// =============== GEMM variant 1: A fp16, W split hi/lo (2 MMA) ===========
// launch_bounds(.,2): GEMM3's 256-block grid quantizes to 1.73 waves at
// 1 CTA/SM; forcing 2 co-resident CTAs collapses it toward one wave.
#define STG2 24576   // A 8K | Bh 8K | Bl 8K
__global__ __launch_bounds__(256, 2) void gemm_w2(
    const __half* __restrict__ A, const __half* __restrict__ Bh,
    const __half* __restrict__ Bl, float* __restrict__ C, int M, int N, int K)
{
    extern __shared__ __align__(128) char smem[];
    uint32_t sb = smem_to_u32(smem);
    int tid = threadIdx.x, lane = tid & 31, wid = tid >> 5;
    int wm = wid & 3, wn = wid >> 2;
    int bx = blockIdx.x, by = blockIdx.y;
    const int NC = K >> 5;

    float acc[2][8][4];
    #pragma unroll
    for (int i = 0; i < 2; i++)
        #pragma unroll
        for (int j = 0; j < 8; j++)
            #pragma unroll
            for (int q = 0; q < 4; q++) acc[i][j][q] = 0.f;

    #define LOAD_W2(ic, s) do { \
        long kof = (long)(ic) * 32; \
        uint32_t st = sb + (s)*STG2; \
        _Pragma("unroll") \
        for (int j = 0; j < 2; j++) { \
            int u = tid + j*256; int row = u >> 2, kc = u & 3; \
            uint32_t sw = tunit(row, kc); \
            long ao = (long)(by*128 + row)*K + kof + kc*8; \
            long bo = (long)(bx*128 + row)*K + kof + kc*8; \
            CP16(st + sw,          A  + ao); \
            CP16(st + 8192 + sw,   Bh + bo); \
            CP16(st + 16384 + sw,  Bl + bo); \
        } \
        CP_COMMIT(); \
    } while (0)

    LOAD_W2(0, 0);
    LOAD_W2(1, 1);

    int lr = lane & 15, lk = lane >> 4;
    for (int ic = 0; ic < NC; ic++) {
        int s = ic - (ic/3)*3;
        if (ic + 1 < NC) CP_WAIT1(); else CP_WAIT0();
        __syncthreads();
        if (ic + 2 < NC) { int s2 = (ic+2) - ((ic+2)/3)*3; LOAD_W2(ic + 2, s2); }

        uint32_t pA = sb + s*STG2, pBh = pA + 8192, pBl = pA + 16384;
        #pragma unroll
        for (int ks = 0; ks < 2; ks++) {
            uint32_t a[2][4], bh[8][2], bl[8][2];
            #pragma unroll
            for (int mt = 0; mt < 2; mt++)
                ldsm_x4(a[mt], pA + tunit(wm*32 + mt*16 + lr, ks*2 + lk));
            #pragma unroll
            for (int bp = 0; bp < 4; bp++) {
                uint32_t off = tunit(wn*64 + bp*16 + lr, ks*2 + lk);
                uint32_t t[4];
                ldsm_x4(t, pBh + off);
                bh[bp*2][0]=t[0]; bh[bp*2][1]=t[2]; bh[bp*2+1][0]=t[1]; bh[bp*2+1][1]=t[3];
                ldsm_x4(t, pBl + off);
                bl[bp*2][0]=t[0]; bl[bp*2][1]=t[2]; bl[bp*2+1][0]=t[1]; bl[bp*2+1][1]=t[3];
            }
            #pragma unroll
            for (int mt = 0; mt < 2; mt++)
                #pragma unroll
                for (int nt = 0; nt < 8; nt++) {
                    mma16816f(acc[mt][nt], a[mt], bh[nt]);
                    mma16816f(acc[mt][nt], a[mt], bl[nt]);
                }
        }
    }

    #pragma unroll
    for (int mt = 0; mt < 2; mt++)
        #pragma unroll
        for (int nt = 0; nt < 8; nt++) {
            long r = by*128 + wm*32 + mt*16 + (lane >> 2);
            long c = bx*128 + wn*64 + nt*8 + (lane & 3)*2;
            *(float2*)&C[r*N + c]     = make_float2(acc[mt][nt][0], acc[mt][nt][1]);
            *(float2*)&C[(r+8)*N + c] = make_float2(acc[mt][nt][2], acc[mt][nt][3]);
        }
}

// ===== causal conv + SiLU + split + l2norm; 4 timesteps per block =========
__global__ __launch_bounds__(256) void conv_kernel(const float* __restrict__ convw)
{
    int t0 = blockIdx.x * 4, b = blockIdx.y;
    int tid = threadIdx.x;
    __shared__ float sy[4][CONVD];

    #pragma unroll
    for (int jt = 0; jt < 4; jt++) {
        int t = t0 + jt;
        long row = (long)(b*T_ + t);
        #pragma unroll
        for (int j = 0; j < 8; j++) {
            int c = tid + j*256;
            float4 w = *(const float4*)(convw + c*4);
            float acc = g_mixed[row*MIXW + c] * w.w;
            if (t >= 1) acc = fmaf(g_mixed[(row-1)*MIXW + c], w.z, acc);
            if (t >= 2) acc = fmaf(g_mixed[(row-2)*MIXW + c], w.y, acc);
            if (t >= 3) acc = fmaf(g_mixed[(row-3)*MIXW + c], w.x, acc);
            sy[jt][c] = acc / (1.f + __expf(-acc));
        }
    }
    __syncthreads();

    int wrp = tid >> 5, lane = tid & 31;
    #pragma unroll
    for (int jt = 0; jt < 4; jt++) {
        long row = (long)(b*T_ + t0 + jt);
        {
            float y0 = sy[jt][wrp*64 + lane], y1 = sy[jt][wrp*64 + 32 + lane];
            float ss = y0*y0 + y1*y1;
            #pragma unroll
            for (int off = 16; off; off >>= 1) ss += __shfl_xor_sync(0xffffffffu, ss, off);
            float rs = rsqrtf(ss + EPS_) * 0.125f;
            g_qn[(row*HK_ + wrp)*64 + lane]      = y0 * rs;
            g_qn[(row*HK_ + wrp)*64 + 32 + lane] = y1 * rs;
        }
        {
            float y0 = sy[jt][KDIM_ + wrp*64 + lane], y1 = sy[jt][KDIM_ + wrp*64 + 32 + lane];
            float ss = y0*y0 + y1*y1;
            #pragma unroll
            for (int off = 16; off; off >>= 1) ss += __shfl_xor_sync(0xffffffffu, ss, off);
            float rs = rsqrtf(ss + EPS_);
            g_kn[(row*HK_ + wrp)*64 + lane]      = y0 * rs;
            g_kn[(row*HK_ + wrp)*64 + 32 + lane] = y1 * rs;
        }
        #pragma unroll
        for (int j = 0; j < 4; j++) {
            int c = tid + j*256;
            g_v[row*VDIM_ + c] = sy[jt][1024 + c];
        }
    }
}

// ======= gated delta recurrence: depth-4 prefetch (R7 verbatim) ===========
#define PF 4
__global__ __launch_bounds__(128) void recurrence_kernel()
{
    int w = blockIdx.x*4 + (threadIdx.x >> 5);    // 0..511
    int lane = threadIdx.x & 31;
    int bh = w >> 4, cg = w & 15;
    int b = bh >> 4, h = bh & 15, kh = h >> 1;
    int colIdx = lane >> 3, rseg = lane & 7;
    int col = cg*4 + colIdx;

    const float* kb = g_kn   + ((long)(b*T_)*HK_ + kh)*64 + rseg*8;
    const float* qb = g_qn   + ((long)(b*T_)*HK_ + kh)*64 + rseg*8;
    const float* vb = g_v    + ((long)(b*T_)*HV_ + h)*64 + col;
    const float* gb = g_gg   + (long)(b*T_)*HV_ + h;
    const float* bb = g_beta + (long)(b*T_)*HV_ + h;
    float*       ob = g_o    + ((long)(b*T_)*HV_ + h)*64 + col;
    const long qs = (long)HK_*64, vs = (long)HV_*64, gs = HV_;

    float S[8], kprev[8], dprev = 0.f;
    #pragma unroll
    for (int i = 0; i < 8; i++) { S[i] = 0.f; kprev[i] = 0.f; }

    float4 pk0[PF], pk1[PF], pq0[PF], pq1[PF];
    float  pv[PF], pg[PF], pb[PF];
    #pragma unroll
    for (int j = 0; j < PF; j++) {
        long o = j;
        pk0[j] = *(const float4*)(kb + o*qs);  pk1[j] = *(const float4*)(kb + o*qs + 4);
        pq0[j] = *(const float4*)(qb + o*qs);  pq1[j] = *(const float4*)(qb + o*qs + 4);
        pv[j] = vb[o*vs];  pg[j] = gb[o*gs];  pb[j] = bb[o*gs];
    }

    for (int t0 = 0; t0 < T_; t0 += PF) {
        #pragma unroll
        for (int j = 0; j < PF; j++) {
            int t = t0 + j;
            float4 k0 = pk0[j], k1 = pk1[j], q0 = pq0[j], q1 = pq1[j];
            float vv = pv[j], gv = pg[j], bv = pb[j];
            if (t + PF < T_) {
                long o = (long)(t + PF);
                pk0[j] = *(const float4*)(kb + o*qs);  pk1[j] = *(const float4*)(kb + o*qs + 4);
                pq0[j] = *(const float4*)(qb + o*qs);  pq1[j] = *(const float4*)(qb + o*qs + 4);
                pv[j] = vb[o*vs];  pg[j] = gb[o*gs];  pb[j] = bb[o*gs];
            }

            float eg = __expf(gv);
            float kc[8] = {k0.x,k0.y,k0.z,k0.w,k1.x,k1.y,k1.z,k1.w};
            float qc[8] = {q0.x,q0.y,q0.z,q0.w,q1.x,q1.y,q1.z,q1.w};
            float kva = 0.f, kvb2 = 0.f, oa = 0.f, ob2 = 0.f, qa = 0.f, qb2 = 0.f;
            #pragma unroll
            for (int i = 0; i < 4; i++) {
                S[i] = fmaf(kprev[i], dprev, S[i]) * eg;
                kva = fmaf(kc[i], S[i], kva);
                oa  = fmaf(qc[i], S[i], oa);
                qa  = fmaf(qc[i], kc[i], qa);
                kprev[i] = kc[i];
            }
            #pragma unroll
            for (int i = 4; i < 8; i++) {
                S[i] = fmaf(kprev[i], dprev, S[i]) * eg;
                kvb2 = fmaf(kc[i], S[i], kvb2);
                ob2  = fmaf(qc[i], S[i], ob2);
                qb2  = fmaf(qc[i], kc[i], qb2);
                kprev[i] = kc[i];
            }
            float kvp = kva + kvb2, op = oa + ob2, qkp = qa + qb2;
            #pragma unroll
            for (int off = 1; off < 8; off <<= 1) {
                kvp += __shfl_xor_sync(0xffffffffu, kvp, off);
                op  += __shfl_xor_sync(0xffffffffu, op,  off);
                qkp += __shfl_xor_sync(0xffffffffu, qkp, off);
            }
            float delta = (vv - kvp) * bv;
            if (rseg == 0) ob[(long)t*vs] = fmaf(qkp, delta, op);
            dprev = delta;
        }
    }
}

// ========== gated RMSNorm * silu(z), emits fp16 for GEMM3 =================
__global__ __launch_bounds__(256) void gnorm_kernel(const float* __restrict__ nw)
{
    int t = blockIdx.x, b = blockIdx.y;
    long row = (long)(b*T_ + t);
    int wrp = threadIdx.x >> 5, lane = threadIdx.x & 31;
    #pragma unroll
    for (int hh = wrp; hh < HV_; hh += 8) {
        float o0 = g_o[(row*HV_ + hh)*64 + lane];
        float o1 = g_o[(row*HV_ + hh)*64 + 32 + lane];
        float ss = o0*o0 + o1*o1;
        #pragma unroll
        for (int off = 16; off; off >>= 1) ss += __shfl_xor_sync(0xffffffffu, ss, off);
        float rs = rsqrtf(ss * (1.f/64.f) + EPS_);
        float z0 = g_mixed[row*MIXW + CONVD + hh*64 + lane];
        float z1 = g_mixed[row*MIXW + CONVD + hh*64 + 32 + lane];
        float v0 = o0 * rs * nw[lane]      * (z0 / (1.f + __expf(-z0)));
        float v1 = o1 * rs * nw[lane + 32] * (z1 / (1.f + __expf(-z1)));
        long i0 = row*VDIM_ + hh*64 + lane;
        g_on[i0]      = __float2half(v0);
        g_on[i0 + 32] = __float2half(v1);
    }
}

// ==========================================================================
extern "C" void kernel_launch(void* const* d_in, const int* in_sizes, int n_in,
                              void* d_out, int out_size)
{
    (void)in_sizes; (void)n_in; (void)out_size;
    const float* hid   = (const float*)d_in[0];
    const float* Wqkv  = (const float*)d_in[1];
    const float* Wz    = (const float*)d_in[2];
    const float* Wb    = (const float*)d_in[3];
    const float* Wa    = (const float*)d_in[4];
    const float* dtb   = (const float*)d_in[5];
    const float* Alog  = (const float*)d_in[6];
    const float* convw = (const float*)d_in[7];
    const float* nw    = (const float*)d_in[8];
    const float* Wout  = (const float*)d_in[9];
    float* out = (float*)d_out;

    float *mixed;
    __half *hh, *w1, *woh, *wol, *on;
    cudaGetSymbolAddress((void**)&mixed, g_mixed);
    cudaGetSymbolAddress((void**)&hh,  g_hid);
    cudaGetSymbolAddress((void**)&w1,  g_w1);
    cudaGetSymbolAddress((void**)&woh, g_woh);  cudaGetSymbolAddress((void**)&wol, g_wol);
    cudaGetSymbolAddress((void**)&on,  g_on);

    static int smem_set = 0;
    if (!smem_set) {
        cudaFuncSetAttribute(gemm_h1, cudaFuncAttributeMaxDynamicSharedMemorySize, 3*STG1);
        cudaFuncSetAttribute(gemm_w2, cudaFuncAttributeMaxDynamicSharedMemorySize, 3*STG2);
        smem_set = 1;
    }

    // fused convert + beta/g (one pass over hid)
    cvtbg_kernel<<<NTOK, 256>>>(hid, hh, Wb, Wa, dtb, Alog);
    // weight conversions
    tconv_f2h<<<dim3(CONVD/32, D_/32), dim3(32,8)>>>(Wqkv, w1, D_, CONVD);
    tconv_f2h<<<dim3(VDIM_/32, D_/32), dim3(32,8)>>>(Wz, w1 + (long)CONVD*D_, D_, VDIM_);
    tconv_f2h2<<<dim3(D_/32, VDIM_/32), dim3(32,8)>>>(Wout, woh, wol, VDIM_, D_);

    // fused GEMM: [mixed | z] = hid @ [Wqkv | Wz]   (single fp16 MMA)
    gemm_h1<<<dim3(MIXW/128, NTOK/128), 256, 3*STG1>>>(hh, w1, mixed, NTOK, MIXW, D_);
    // conv + silu + split + l2norm  (4 timesteps per block)
    conv_kernel<<<dim3(T_/4, B_), 256>>>(convw);
    // recurrence (R7 verbatim)
    recurrence_kernel<<<128, 128>>>();
    // gated RMSNorm -> fp16
    gnorm_kernel<<<dim3(T_, B_), 256>>>(nw);
    // GEMM3: out = on @ Wout  (W compensated, 2 MMA, 2 CTAs/SM)
    gemm_w2<<<dim3(D_/128, NTOK/128), 256, 3*STG2>>>(on, woh, wol, out, NTOK, D_, VDIM_);
}